// round 12
// baseline (speedup 1.0000x reference)
#include <cuda_runtime.h>
#include <cuda_fp16.h>
#include <math.h>
#include <stdint.h>

#define BB 8192
#define DD 768
#define GH 384
#define EE 8
#define HH 3072
#define LN_EPS 1e-5f

// ---------------- scratch (static device globals) ----------------
__device__ __half g_ht [(size_t)BB * DD];          // LN output, half hi
__device__ __half g_htl[(size_t)BB * DD];          // LN output, half lo
__device__ float  g_g1 [(size_t)BB * GH];          // gating hidden (fp32-faithful)
__device__ __half g_hid[(size_t)EE * BB * HH];     // expert hidden, half
__device__ __half g_w1t[(size_t)EE * HH * DD];     // ew1^T [e][H][D], half (K-major)
__device__ __half g_w2t[(size_t)EE * DD * HH];     // ew2^T [e][D][H], half (K-major)
__device__ __half g_gw1h[(size_t)GH * DD];         // gw1^T hi [Gh][D]
__device__ __half g_gw1l[(size_t)GH * DD];         // gw1^T lo [Gh][D]
__device__ float  g_w  [(size_t)BB * 2];
__device__ int    g_i  [(size_t)BB * 2];

// ---------------- helpers ----------------
__device__ __forceinline__ float gelu_erf(float x) {
    return 0.5f * x * (1.0f + erff(x * 0.70710678118654752f));
}
__device__ __forceinline__ uint32_t s2u(const void* p) {
    uint32_t a;
    asm("{ .reg .u64 t; cvta.to.shared.u64 t, %1; cvt.u32.u64 %0, t; }" : "=r"(a) : "l"(p));
    return a;
}

#define SWZ(off) ((uint32_t)(off) ^ (((uint32_t)(off) >> 3) & 0x70u))

#define CPA16(dst, src) \
    asm volatile("cp.async.cg.shared.global [%0], [%1], 16;" :: "r"(dst), "l"(src))
#define CPCOMMIT() asm volatile("cp.async.commit_group;" ::: "memory")
#define CPWAIT0()  asm volatile("cp.async.wait_group 0;" ::: "memory")
#define CPWAIT1()  asm volatile("cp.async.wait_group 1;" ::: "memory")

#define LDSM4(r, addr) \
    asm volatile("ldmatrix.sync.aligned.m8n8.x4.shared.b16 {%0,%1,%2,%3}, [%4];" \
        : "=r"((r)[0]), "=r"((r)[1]), "=r"((r)[2]), "=r"((r)[3]) : "r"(addr))

__device__ __forceinline__ void mma_f16(float c[4], const uint32_t a[4],
                                        uint32_t b0, uint32_t b1) {
    asm volatile(
        "mma.sync.aligned.m16n8k16.row.col.f32.f16.f16.f32 "
        "{%0,%1,%2,%3}, {%4,%5,%6,%7}, {%8,%9}, {%0,%1,%2,%3};"
        : "+f"(c[0]), "+f"(c[1]), "+f"(c[2]), "+f"(c[3])
        : "r"(a[0]), "r"(a[1]), "r"(a[2]), "r"(a[3]), "r"(b0), "r"(b1));
}

// ===========================================================================
// PREP: merged ln + transpose(ew1) + transpose(ew2) + split-transpose(gw1)
// ===========================================================================
#define NB_LN   (BB)
#define NB_T1   ((HH / 32) * (DD / 32) * EE)
#define NB_T2   ((DD / 32) * (HH / 32) * EE)
#define NB_TS   ((GH / 32) * (DD / 32))
#define NB_PREP (NB_LN + NB_T1 + NB_T2 + NB_TS)

__device__ void ln_body(int b, const float* __restrict__ x,
                        const float* __restrict__ gamma,
                        const float* __restrict__ beta) {
    const float* row = x + (size_t)b * DD;
    float s = 0.f, ss = 0.f;
    for (int d = threadIdx.x; d < DD; d += 256) {
        float v = row[d];
        s += v; ss += v * v;
    }
    #pragma unroll
    for (int o = 16; o; o >>= 1) {
        s  += __shfl_xor_sync(0xffffffffu, s, o);
        ss += __shfl_xor_sync(0xffffffffu, ss, o);
    }
    __shared__ float rs[8], rss[8];
    int w = threadIdx.x >> 5, l = threadIdx.x & 31;
    if (l == 0) { rs[w] = s; rss[w] = ss; }
    __syncthreads();
    if (w == 0) {
        s  = (l < 8) ? rs[l]  : 0.f;
        ss = (l < 8) ? rss[l] : 0.f;
        #pragma unroll
        for (int o = 4; o; o >>= 1) {
            s  += __shfl_xor_sync(0xffffffffu, s, o);
            ss += __shfl_xor_sync(0xffffffffu, ss, o);
        }
        if (l == 0) { rs[0] = s; rss[0] = ss; }
    }
    __syncthreads();
    float mu  = rs[0] * (1.0f / DD);
    float var = rss[0] * (1.0f / DD) - mu * mu;
    float inv = rsqrtf(var + LN_EPS);
    for (int d = threadIdx.x; d < DD; d += 256) {
        float v = (row[d] - mu) * inv * gamma[d] + beta[d];
        __half hi = __float2half_rn(v);
        g_ht [(size_t)b * DD + d] = hi;
        g_htl[(size_t)b * DD + d] = __float2half_rn(v - __half2float(hi));
    }
}

__device__ void transpose_body(int bx, int by, const float* __restrict__ src,
                               __half* __restrict__ dst, int R, int C) {
    __shared__ float t[32][33];
    int tx = threadIdx.x & 31, ty = threadIdx.x >> 5;
    int c0 = bx * 32, r0 = by * 32;
    #pragma unroll
    for (int j = 0; j < 32; j += 8)
        t[ty + j][tx] = src[(size_t)(r0 + ty + j) * C + c0 + tx];
    __syncthreads();
    #pragma unroll
    for (int j = 0; j < 32; j += 8)
        dst[(size_t)(c0 + ty + j) * R + r0 + tx] =
            __float2half_rn(t[tx][ty + j]);
}

__device__ void transpose_split_body(int bx, int by, const float* __restrict__ src,
                                     __half* __restrict__ dh, __half* __restrict__ dl,
                                     int R, int C) {
    __shared__ float t2[32][33];
    int tx = threadIdx.x & 31, ty = threadIdx.x >> 5;
    int c0 = bx * 32, r0 = by * 32;
    #pragma unroll
    for (int j = 0; j < 32; j += 8)
        t2[ty + j][tx] = src[(size_t)(r0 + ty + j) * C + c0 + tx];
    __syncthreads();
    #pragma unroll
    for (int j = 0; j < 32; j += 8) {
        float v = t2[tx][ty + j];
        __half hi = __float2half_rn(v);
        size_t idx = (size_t)(c0 + ty + j) * R + r0 + tx;
        dh[idx] = hi;
        dl[idx] = __float2half_rn(v - __half2float(hi));
    }
}

__global__ __launch_bounds__(256)
void prep_kernel(const float* __restrict__ pooler,
                 const float* __restrict__ ln_gamma,
                 const float* __restrict__ ln_beta,
                 const float* __restrict__ ew1,
                 const float* __restrict__ ew2,
                 const float* __restrict__ gw1) {
    int bid = blockIdx.x;
    if (bid < NB_LN) {
        ln_body(bid, pooler, ln_gamma, ln_beta);
        return;
    }
    bid -= NB_LN;
    if (bid < NB_T1) {       // ew1 [e][D][H] -> g_w1t [e][H][D]
        const int XB = HH / 32;
        int e = bid / (XB * (DD / 32));
        int r = bid % (XB * (DD / 32));
        transpose_body(r % XB, r / XB, ew1 + (size_t)e * DD * HH,
                       g_w1t + (size_t)e * DD * HH, DD, HH);
        return;
    }
    bid -= NB_T1;
    if (bid < NB_T2) {       // ew2 [e][H][D] -> g_w2t [e][D][H]
        const int XB = DD / 32;
        int e = bid / (XB * (HH / 32));
        int r = bid % (XB * (HH / 32));
        transpose_body(r % XB, r / XB, ew2 + (size_t)e * HH * DD,
                       g_w2t + (size_t)e * HH * DD, HH, DD);
        return;
    }
    bid -= NB_T2;
    {                        // gw1 [D][Gh] -> hi/lo [Gh][D]
        const int XB = GH / 32;
        transpose_split_body(bid % XB, bid / XB, gw1, g_gw1h, g_gw1l, DD, GH);
    }
}

// ===========================================================================
// Gate split-fp16 GEMM: CTA 64x64, warp 32x16 (2x4), BK=64, 3-stage, occ 2.
// acc = AhBh + AhBl + AlBh.  LDSM addresses via hoisted-offset + XOR trick.
// ===========================================================================
__global__ __launch_bounds__(256, 2)
void gate_gemm_kernel(const float* __restrict__ bias) {
    constexpr int K = DD, BK = 64, NIT = K / BK;
    constexpr int TB = 64 * 128;               // 8 KB per tile
    constexpr int STAGE_BYTES = 4 * TB;        // 32 KB
    constexpr int STAGES = 3;

    extern __shared__ char smem[];
    const int bx = blockIdx.x % (GH / 64);
    const int by = blockIdx.x / (GH / 64);
    const int n0 = bx * 64;
    const int m0 = by * 64;
    const __half* Ah = g_ht;
    const __half* Al = g_htl;
    const __half* Bh = g_gw1h;
    const __half* Bl = g_gw1l;

    const int tid   = threadIdx.x;
    const int warp  = tid >> 5;
    const int lane  = tid & 31;
    const int warpM = warp >> 2;
    const int warpN = warp & 3;
    const int hi    = lane >> 4;

    const uint32_t sbase = s2u(smem);

    // loop-invariant swizzled offsets (ks=0); addr(ks) = addr(0) ^ (32*ks)
    uint32_t aOff[2], bOff;
    #pragma unroll
    for (int ii = 0; ii < 2; ii++) {
        int row = warpM * 32 + ii * 16 + (lane & 15);
        aOff[ii] = SWZ((uint32_t)(row * 128 + hi * 16));
    }
    {
        int row = warpN * 16 + (lane & 15);
        bOff = SWZ((uint32_t)(row * 128 + hi * 16));
    }

    auto load_stage = [&](int s, int k0) {
        uint32_t aH = sbase + (uint32_t)s * STAGE_BYTES;
        uint32_t aL = aH + TB, bH = aH + 2 * TB, bL = aH + 3 * TB;
        #pragma unroll
        for (int t = 0; t < 2; t++) {
            int id = tid + t * 256;
            int row = id >> 3, c = id & 7;
            uint32_t o = SWZ(row * 128 + c * 16);
            CPA16(aH + o, Ah + (size_t)(m0 + row) * K + k0 + c * 8);
            CPA16(aL + o, Al + (size_t)(m0 + row) * K + k0 + c * 8);
            CPA16(bH + o, Bh + (size_t)(n0 + row) * K + k0 + c * 8);
            CPA16(bL + o, Bl + (size_t)(n0 + row) * K + k0 + c * 8);
        }
    };

    load_stage(0, 0);   CPCOMMIT();
    load_stage(1, BK);  CPCOMMIT();

    float acc[2][2][4] = {};

    for (int i = 0; i < NIT; i++) {
        if (i + 1 < NIT) { CPWAIT1(); } else { CPWAIT0(); }
        __syncthreads();
        if (i + 2 < NIT) { load_stage((i + 2) % STAGES, (i + 2) * BK); CPCOMMIT(); }

        const uint32_t aH = sbase + (uint32_t)(i % STAGES) * STAGE_BYTES;
        uint32_t aAdrH[2], aAdrL[2], bAdrH, bAdrL;
        #pragma unroll
        for (int ii = 0; ii < 2; ii++) {
            aAdrH[ii] = aH + aOff[ii];
            aAdrL[ii] = aH + TB + aOff[ii];
        }
        bAdrH = aH + 2 * TB + bOff;
        bAdrL = aH + 3 * TB + bOff;

        #pragma unroll
        for (int ks = 0; ks < 4; ks++) {
            const uint32_t x = (uint32_t)(ks * 32);
            uint32_t afh[2][4], afl[2][4], bfh[4], bfl[4];
            #pragma unroll
            for (int ii = 0; ii < 2; ii++) {
                LDSM4(afh[ii], aAdrH[ii] ^ x);
                LDSM4(afl[ii], aAdrL[ii] ^ x);
            }
            LDSM4(bfh, bAdrH ^ x);
            LDSM4(bfl, bAdrL ^ x);
            #pragma unroll
            for (int ii = 0; ii < 2; ii++) {
                mma_f16(acc[ii][0], afh[ii], bfh[0], bfh[2]);
                mma_f16(acc[ii][1], afh[ii], bfh[1], bfh[3]);
                mma_f16(acc[ii][0], afh[ii], bfl[0], bfl[2]);
                mma_f16(acc[ii][1], afh[ii], bfl[1], bfl[3]);
                mma_f16(acc[ii][0], afl[ii], bfh[0], bfh[2]);
                mma_f16(acc[ii][1], afl[ii], bfh[1], bfh[3]);
            }
        }
    }

    const int r  = lane >> 2;
    const int c2 = (lane & 3) * 2;
    #pragma unroll
    for (int ii = 0; ii < 2; ii++) {
        int row0 = m0 + warpM * 32 + ii * 16 + r;
        int row1 = row0 + 8;
        #pragma unroll
        for (int j = 0; j < 2; j++) {
            int gcol = n0 + warpN * 16 + j * 8 + c2;
            float b0 = bias[gcol], b1 = bias[gcol + 1];
            float v0 = gelu_erf(acc[ii][j][0] + b0);
            float v1 = gelu_erf(acc[ii][j][1] + b1);
            float v2 = gelu_erf(acc[ii][j][2] + b0);
            float v3 = gelu_erf(acc[ii][j][3] + b1);
            *(float2*)(g_g1 + (size_t)row0 * GH + gcol) = make_float2(v0, v1);
            *(float2*)(g_g1 + (size_t)row1 * GH + gcol) = make_float2(v2, v3);
        }
    }
}

// ===========================================================================
// Expert fp16 GEMM: CTA 128x128, warp 64x32, BK=64, 3-stage cp.async, occ 2.
// LDSM addresses via hoisted-offset + XOR trick.
// ===========================================================================
template <int K, int N, bool GELU, bool EOUT>
__global__ __launch_bounds__(256, 2)
void hgemm(const __half* __restrict__ A, size_t aStride,
           const __half* __restrict__ Bt,
           const float* __restrict__ bias,
           void* __restrict__ Cout) {
    constexpr int BK = 64;
    constexpr int NIT = K / BK;
    constexpr int ABYTES = 128 * 128;
    constexpr int STAGE_BYTES = 2 * ABYTES;
    constexpr int STAGES = 3;

    extern __shared__ char smem[];
    const int e  = blockIdx.z;
    const int n0 = blockIdx.x * 128;
    const int m0 = blockIdx.y * 128;
    A    += (size_t)e * aStride;
    Bt   += (size_t)e * (size_t)N * K;
    bias += (size_t)e * N;

    const int tid   = threadIdx.x;
    const int warp  = tid >> 5;
    const int lane  = tid & 31;
    const int warpM = warp >> 2;
    const int warpN = warp & 3;
    const int hi    = lane >> 4;

    const uint32_t sbase = s2u(smem);

    // loop-invariant swizzled LDSM offsets at ks=0; addr(ks) = addr(0) ^ (32*ks)
    uint32_t aOff[4], bOff[2];
    #pragma unroll
    for (int ii = 0; ii < 4; ii++) {
        int row = warpM * 64 + ii * 16 + (lane & 15);
        aOff[ii] = SWZ((uint32_t)(row * 128 + hi * 16));
    }
    #pragma unroll
    for (int jp = 0; jp < 2; jp++) {
        int row = warpN * 32 + jp * 16 + (lane & 15);
        bOff[jp] = SWZ((uint32_t)(row * 128 + hi * 16));
    }

    auto load_stage = [&](int s, int k0) {
        uint32_t aB = sbase + (uint32_t)s * STAGE_BYTES;
        uint32_t bB = aB + ABYTES;
        #pragma unroll
        for (int t = 0; t < 4; t++) {
            int id = tid + t * 256;
            int row = id >> 3, c = id & 7;
            CPA16(aB + SWZ(row * 128 + c * 16), A + (size_t)(m0 + row) * K + k0 + c * 8);
        }
        #pragma unroll
        for (int t = 0; t < 4; t++) {
            int id = tid + t * 256;
            int row = id >> 3, c = id & 7;
            CPA16(bB + SWZ(row * 128 + c * 16), Bt + (size_t)(n0 + row) * K + k0 + c * 8);
        }
    };

    load_stage(0, 0);   CPCOMMIT();
    load_stage(1, BK);  CPCOMMIT();

    float acc[4][4][4] = {};

    for (int i = 0; i < NIT; i++) {
        if (i + 1 < NIT) { CPWAIT1(); } else { CPWAIT0(); }
        __syncthreads();

        if (i + 2 < NIT) {
            load_stage((i + 2) % STAGES, (i + 2) * BK);
            CPCOMMIT();
        }

        const uint32_t aB = sbase + (uint32_t)(i % STAGES) * STAGE_BYTES;
        const uint32_t bB = aB + ABYTES;
        uint32_t aAdr[4], bAdr[2];
        #pragma unroll
        for (int ii = 0; ii < 4; ii++) aAdr[ii] = aB + aOff[ii];
        #pragma unroll
        for (int jp = 0; jp < 2; jp++) bAdr[jp] = bB + bOff[jp];

        #pragma unroll
        for (int ks = 0; ks < 4; ks++) {
            const uint32_t x = (uint32_t)(ks * 32);
            uint32_t afr[4][4], bfr[2][4];
            #pragma unroll
            for (int ii = 0; ii < 4; ii++) LDSM4(afr[ii], aAdr[ii] ^ x);
            #pragma unroll
            for (int jp = 0; jp < 2; jp++) LDSM4(bfr[jp], bAdr[jp] ^ x);
            #pragma unroll
            for (int ii = 0; ii < 4; ii++) {
                #pragma unroll
                for (int jp = 0; jp < 2; jp++) {
                    mma_f16(acc[ii][jp * 2 + 0], afr[ii], bfr[jp][0], bfr[jp][2]);
                    mma_f16(acc[ii][jp * 2 + 1], afr[ii], bfr[jp][1], bfr[jp][3]);
                }
            }
        }
    }

    const int r  = lane >> 2;
    const int c2 = (lane & 3) * 2;
    #pragma unroll
    for (int ii = 0; ii < 4; ii++) {
        int row0 = m0 + warpM * 64 + ii * 16 + r;
        int row1 = row0 + 8;
        #pragma unroll
        for (int j = 0; j < 4; j++) {
            int gcol = n0 + warpN * 32 + j * 8 + c2;
            float b0 = bias[gcol], b1 = bias[gcol + 1];
            float v0 = acc[ii][j][0] + b0;
            float v1 = acc[ii][j][1] + b1;
            float v2 = acc[ii][j][2] + b0;
            float v3 = acc[ii][j][3] + b1;
            if (GELU) {
                v0 = gelu_erf(v0); v1 = gelu_erf(v1);
                v2 = gelu_erf(v2); v3 = gelu_erf(v3);
            }
            if (EOUT) {
                float* C = (float*)Cout;
                *(float2*)(C + ((size_t)row0 * EE + e) * DD + gcol) = make_float2(v0, v1);
                *(float2*)(C + ((size_t)row1 * EE + e) * DD + gcol) = make_float2(v2, v3);
            } else {
                __half* C = (__half*)Cout;
                *(__half2*)(C + ((size_t)e * BB + row0) * (size_t)N + gcol) =
                    __floats2half2_rn(v0, v1);
                *(__half2*)(C + ((size_t)e * BB + row1) * (size_t)N + gcol) =
                    __floats2half2_rn(v2, v3);
            }
        }
    }
}

// ---------------------------------------------------------------------------
// gating logits + softmax + top-2
// ---------------------------------------------------------------------------
__global__ void gate_kernel(const float* __restrict__ gw2,
                            const float* __restrict__ gb2,
                            float* __restrict__ gate_out) {
    int warp = threadIdx.x >> 5, lane = threadIdx.x & 31;
    int b = blockIdx.x * 8 + warp;
    const float* g1 = g_g1 + (size_t)b * GH;
    float logit[EE];
    #pragma unroll
    for (int e = 0; e < EE; e++) {
        float acc = 0.f;
        for (int k = lane; k < GH; k += 32) acc += g1[k] * gw2[k * EE + e];
        #pragma unroll
        for (int o = 16; o; o >>= 1) acc += __shfl_xor_sync(0xffffffffu, acc, o);
        logit[e] = acc + gb2[e];
    }
    if (lane == 0) {
        float mx = logit[0];
        #pragma unroll
        for (int e = 1; e < EE; e++) mx = fmaxf(mx, logit[e]);
        float p[EE]; float sum = 0.f;
        #pragma unroll
        for (int e = 0; e < EE; e++) { p[e] = expf(logit[e] - mx); sum += p[e]; }
        float invs = 1.0f / sum;
        #pragma unroll
        for (int e = 0; e < EE; e++) {
            p[e] *= invs;
            gate_out[(size_t)b * EE + e] = p[e];
        }
        int i0 = 0;
        #pragma unroll
        for (int e = 1; e < EE; e++) if (p[e] > p[i0]) i0 = e;
        int i1 = (i0 == 0) ? 1 : 0;
        #pragma unroll
        for (int e = 0; e < EE; e++) if (e != i0 && p[e] > p[i1]) i1 = e;
        float w0 = p[i0], w1 = p[i1], s = w0 + w1;
        g_w[b * 2 + 0] = w0 / s;
        g_w[b * 2 + 1] = w1 / s;
        g_i[b * 2 + 0] = i0;
        g_i[b * 2 + 1] = i1;
    }
}

// ---------------------------------------------------------------------------
// combine: weighted sum of top-2 expert outputs (float4 vectorized)
// ---------------------------------------------------------------------------
__global__ __launch_bounds__(192)
void combine_kernel(const float* __restrict__ eo, float* __restrict__ out) {
    int b = blockIdx.x;
    int i0 = g_i[b * 2], i1 = g_i[b * 2 + 1];
    float w0 = g_w[b * 2], w1 = g_w[b * 2 + 1];
    const float4* r0 = (const float4*)(eo + (size_t)b * EE * DD + (size_t)i0 * DD);
    const float4* r1 = (const float4*)(eo + (size_t)b * EE * DD + (size_t)i1 * DD);
    float4* o = (float4*)(out + (size_t)b * DD);
    int t = threadIdx.x;
    float4 a = r0[t], c = r1[t];
    float4 v;
    v.x = w0 * a.x + w1 * c.x;
    v.y = w0 * a.y + w1 * c.y;
    v.z = w0 * a.z + w1 * c.z;
    v.w = w0 * a.w + w1 * c.w;
    o[t] = v;
}

// ---------------------------------------------------------------------------
extern "C" void kernel_launch(void* const* d_in, const int* in_sizes, int n_in,
                              void* d_out, int out_size) {
    const float* pooler   = (const float*)d_in[0];
    const float* ln_gamma = (const float*)d_in[1];
    const float* ln_beta  = (const float*)d_in[2];
    const float* gw1      = (const float*)d_in[3];
    const float* gb1      = (const float*)d_in[4];
    const float* gw2      = (const float*)d_in[5];
    const float* gb2      = (const float*)d_in[6];
    const float* ew1      = (const float*)d_in[7];
    const float* eb1      = (const float*)d_in[8];
    const float* ew2      = (const float*)d_in[9];
    const float* eb2      = (const float*)d_in[10];

    float* out        = (float*)d_out;
    float* out_result = out;                          // [B, D]
    float* out_gate   = out + (size_t)BB * DD;        // [B, E]
    float* out_eo     = out_gate + (size_t)BB * EE;   // [B, E, D]

    __half *ht_ptr, *hid_ptr, *w1t_ptr, *w2t_ptr;
    cudaGetSymbolAddress((void**)&ht_ptr,  g_ht);
    cudaGetSymbolAddress((void**)&hid_ptr, g_hid);
    cudaGetSymbolAddress((void**)&w1t_ptr, g_w1t);
    cudaGetSymbolAddress((void**)&w2t_ptr, g_w2t);

    const int SMEM = 3 * 32768;   // 96 KB
    cudaFuncSetAttribute(hgemm<DD, HH, true,  false>,
                         cudaFuncAttributeMaxDynamicSharedMemorySize, SMEM);
    cudaFuncSetAttribute(hgemm<HH, DD, false, true>,
                         cudaFuncAttributeMaxDynamicSharedMemorySize, SMEM);
    cudaFuncSetAttribute(gate_gemm_kernel,
                         cudaFuncAttributeMaxDynamicSharedMemorySize, SMEM);

    // 1) prep: LN + all weight transposes/splits, fully parallel
    prep_kernel<<<NB_PREP, 256>>>(pooler, ln_gamma, ln_beta, ew1, ew2, gw1);

    // 2) gating hidden (split-fp16, fp32-faithful)
    gate_gemm_kernel<<<(GH / 64) * (BB / 64), 256, SMEM>>>(gb1);

    // 3) gating logits + softmax + top2
    gate_kernel<<<BB / 8, 256>>>(gw2, gb2, out_gate);

    // 4) expert hidden: hid[e] = half(gelu(h @ ew1[e] + eb1[e]))
    hgemm<DD, HH, true, false><<<dim3(HH / 128, BB / 128, EE), 256, SMEM>>>(
        ht_ptr, 0, w1t_ptr, eb1, hid_ptr);

    // 5) expert outputs: eo[:,e,:] = hid[e] @ ew2[e] + eb2[e]
    hgemm<HH, DD, false, true><<<dim3(DD / 128, BB / 128, EE), 256, SMEM>>>(
        hid_ptr, (size_t)BB * HH, w2t_ptr, eb2, out_eo);

    // 6) combine top-2
    combine_kernel<<<BB, 192>>>(out_eo, out_result);
}

// round 13
// speedup vs baseline: 1.0737x; 1.0737x over previous
#include <cuda_runtime.h>
#include <cuda.h>
#include <cuda_fp16.h>
#include <math.h>
#include <stdint.h>

#define BB 8192
#define DD 768
#define GH 384
#define EE 8
#define HH 3072
#define LN_EPS 1e-5f

// ---------------- scratch (static device globals) ----------------
__device__ __half g_ht [(size_t)BB * DD];          // LN output, half hi
__device__ __half g_htl[(size_t)BB * DD];          // LN output, half lo
__device__ float  g_g1 [(size_t)BB * GH];          // gating hidden (fp32-faithful)
__device__ __half g_hid[(size_t)EE * BB * HH];     // expert hidden, half
__device__ __half g_w1t[(size_t)EE * HH * DD];     // ew1^T [e][H][D], half (K-major)
__device__ __half g_w2t[(size_t)EE * DD * HH];     // ew2^T [e][D][H], half (K-major)
__device__ __half g_gw1h[(size_t)GH * DD];         // gw1^T hi [Gh][D]
__device__ __half g_gw1l[(size_t)GH * DD];         // gw1^T lo [Gh][D]
__device__ float  g_w  [(size_t)BB * 2];
__device__ int    g_i  [(size_t)BB * 2];

// ---------------- helpers ----------------
__device__ __forceinline__ float gelu_erf(float x) {
    return 0.5f * x * (1.0f + erff(x * 0.70710678118654752f));
}
__device__ __forceinline__ uint32_t s2u(const void* p) {
    uint32_t a;
    asm("{ .reg .u64 t; cvta.to.shared.u64 t, %1; cvt.u32.u64 %0, t; }" : "=r"(a) : "l"(p));
    return a;
}

#define SWZ(off) ((uint32_t)(off) ^ (((uint32_t)(off) >> 3) & 0x70u))

#define CPA16(dst, src) \
    asm volatile("cp.async.cg.shared.global [%0], [%1], 16;" :: "r"(dst), "l"(src))
#define CPCOMMIT() asm volatile("cp.async.commit_group;" ::: "memory")
#define CPWAIT0()  asm volatile("cp.async.wait_group 0;" ::: "memory")
#define CPWAIT1()  asm volatile("cp.async.wait_group 1;" ::: "memory")

#define LDSM4(r, addr) \
    asm volatile("ldmatrix.sync.aligned.m8n8.x4.shared.b16 {%0,%1,%2,%3}, [%4];" \
        : "=r"((r)[0]), "=r"((r)[1]), "=r"((r)[2]), "=r"((r)[3]) : "r"(addr))

__device__ __forceinline__ void mma_f16(float c[4], const uint32_t a[4],
                                        uint32_t b0, uint32_t b1) {
    asm volatile(
        "mma.sync.aligned.m16n8k16.row.col.f32.f16.f16.f32 "
        "{%0,%1,%2,%3}, {%4,%5,%6,%7}, {%8,%9}, {%0,%1,%2,%3};"
        : "+f"(c[0]), "+f"(c[1]), "+f"(c[2]), "+f"(c[3])
        : "r"(a[0]), "r"(a[1]), "r"(a[2]), "r"(a[3]), "r"(b0), "r"(b1));
}

// ---- TMA / mbarrier ----
#define MBAR_INIT(addr, cnt) \
    asm volatile("mbarrier.init.shared.b64 [%0], %1;" :: "r"(addr), "r"((uint32_t)(cnt)) : "memory")
#define MBAR_EXPECT(addr, bytes) \
    asm volatile("mbarrier.arrive.expect_tx.shared.b64 _, [%0], %1;" \
                 :: "r"(addr), "r"((uint32_t)(bytes)) : "memory")
#define MBAR_WAIT(addr, ph) do {                                                   \
    uint32_t _done = 0;                                                            \
    while (!_done) {                                                               \
        asm volatile("{\n\t.reg .pred p;\n\t"                                      \
            "mbarrier.try_wait.parity.acquire.cta.shared::cta.b64 p, [%1], %2, 0x989680;\n\t" \
            "selp.b32 %0, 1, 0, p;\n\t}"                                           \
            : "=r"(_done) : "r"(addr), "r"((uint32_t)(ph)) : "memory");            \
    } } while (0)
#define TMA_LOAD3(smem_addr, map_ptr, cx, cy, cz, mbar) \
    asm volatile("cp.async.bulk.tensor.3d.shared::cta.global.tile.mbarrier::complete_tx::bytes " \
                 "[%0], [%1, {%2, %3, %4}], [%5];" \
                 :: "r"(smem_addr), "l"(map_ptr), "r"((int)(cx)), "r"((int)(cy)), \
                    "r"((int)(cz)), "r"(mbar) : "memory")

// ===========================================================================
// PREP: merged ln + transpose(ew1) + transpose(ew2) + split-transpose(gw1)
// ===========================================================================
#define NB_LN   (BB)
#define NB_T1   ((HH / 32) * (DD / 32) * EE)
#define NB_T2   ((DD / 32) * (HH / 32) * EE)
#define NB_TS   ((GH / 32) * (DD / 32))
#define NB_PREP (NB_LN + NB_T1 + NB_T2 + NB_TS)

__device__ void ln_body(int b, const float* __restrict__ x,
                        const float* __restrict__ gamma,
                        const float* __restrict__ beta) {
    const float* row = x + (size_t)b * DD;
    float s = 0.f, ss = 0.f;
    for (int d = threadIdx.x; d < DD; d += 256) {
        float v = row[d];
        s += v; ss += v * v;
    }
    #pragma unroll
    for (int o = 16; o; o >>= 1) {
        s  += __shfl_xor_sync(0xffffffffu, s, o);
        ss += __shfl_xor_sync(0xffffffffu, ss, o);
    }
    __shared__ float rs[8], rss[8];
    int w = threadIdx.x >> 5, l = threadIdx.x & 31;
    if (l == 0) { rs[w] = s; rss[w] = ss; }
    __syncthreads();
    if (w == 0) {
        s  = (l < 8) ? rs[l]  : 0.f;
        ss = (l < 8) ? rss[l] : 0.f;
        #pragma unroll
        for (int o = 4; o; o >>= 1) {
            s  += __shfl_xor_sync(0xffffffffu, s, o);
            ss += __shfl_xor_sync(0xffffffffu, ss, o);
        }
        if (l == 0) { rs[0] = s; rss[0] = ss; }
    }
    __syncthreads();
    float mu  = rs[0] * (1.0f / DD);
    float var = rss[0] * (1.0f / DD) - mu * mu;
    float inv = rsqrtf(var + LN_EPS);
    for (int d = threadIdx.x; d < DD; d += 256) {
        float v = (row[d] - mu) * inv * gamma[d] + beta[d];
        __half hi = __float2half_rn(v);
        g_ht [(size_t)b * DD + d] = hi;
        g_htl[(size_t)b * DD + d] = __float2half_rn(v - __half2float(hi));
    }
}

__device__ void transpose_body(int bx, int by, const float* __restrict__ src,
                               __half* __restrict__ dst, int R, int C) {
    __shared__ float t[32][33];
    int tx = threadIdx.x & 31, ty = threadIdx.x >> 5;
    int c0 = bx * 32, r0 = by * 32;
    #pragma unroll
    for (int j = 0; j < 32; j += 8)
        t[ty + j][tx] = src[(size_t)(r0 + ty + j) * C + c0 + tx];
    __syncthreads();
    #pragma unroll
    for (int j = 0; j < 32; j += 8)
        dst[(size_t)(c0 + ty + j) * R + r0 + tx] =
            __float2half_rn(t[tx][ty + j]);
}

__device__ void transpose_split_body(int bx, int by, const float* __restrict__ src,
                                     __half* __restrict__ dh, __half* __restrict__ dl,
                                     int R, int C) {
    __shared__ float t2[32][33];
    int tx = threadIdx.x & 31, ty = threadIdx.x >> 5;
    int c0 = bx * 32, r0 = by * 32;
    #pragma unroll
    for (int j = 0; j < 32; j += 8)
        t2[ty + j][tx] = src[(size_t)(r0 + ty + j) * C + c0 + tx];
    __syncthreads();
    #pragma unroll
    for (int j = 0; j < 32; j += 8) {
        float v = t2[tx][ty + j];
        __half hi = __float2half_rn(v);
        size_t idx = (size_t)(c0 + ty + j) * R + r0 + tx;
        dh[idx] = hi;
        dl[idx] = __float2half_rn(v - __half2float(hi));
    }
}

__global__ __launch_bounds__(256)
void prep_kernel(const float* __restrict__ pooler,
                 const float* __restrict__ ln_gamma,
                 const float* __restrict__ ln_beta,
                 const float* __restrict__ ew1,
                 const float* __restrict__ ew2,
                 const float* __restrict__ gw1) {
    int bid = blockIdx.x;
    if (bid < NB_LN) {
        ln_body(bid, pooler, ln_gamma, ln_beta);
        return;
    }
    bid -= NB_LN;
    if (bid < NB_T1) {       // ew1 [e][D][H] -> g_w1t [e][H][D]
        const int XB = HH / 32;
        int e = bid / (XB * (DD / 32));
        int r = bid % (XB * (DD / 32));
        transpose_body(r % XB, r / XB, ew1 + (size_t)e * DD * HH,
                       g_w1t + (size_t)e * DD * HH, DD, HH);
        return;
    }
    bid -= NB_T1;
    if (bid < NB_T2) {       // ew2 [e][H][D] -> g_w2t [e][D][H]
        const int XB = DD / 32;
        int e = bid / (XB * (HH / 32));
        int r = bid % (XB * (HH / 32));
        transpose_body(r % XB, r / XB, ew2 + (size_t)e * HH * DD,
                       g_w2t + (size_t)e * HH * DD, HH, DD);
        return;
    }
    bid -= NB_T2;
    {                        // gw1 [D][Gh] -> hi/lo [Gh][D]
        const int XB = GH / 32;
        transpose_split_body(bid % XB, bid / XB, gw1, g_gw1h, g_gw1l, DD, GH);
    }
}

// ===========================================================================
// Gate split-fp16 GEMM (R11 version): CTA 64x64, BK=64, 3-stage, occ 2.
// ===========================================================================
__global__ __launch_bounds__(256, 2)
void gate_gemm_kernel(const float* __restrict__ bias) {
    constexpr int K = DD, BK = 64, NIT = K / BK;
    constexpr int TB = 64 * 128;
    constexpr int STAGE_BYTES = 4 * TB;
    constexpr int STAGES = 3;

    extern __shared__ __align__(1024) char smem[];
    const int bx = blockIdx.x % (GH / 64);
    const int by = blockIdx.x / (GH / 64);
    const int n0 = bx * 64;
    const int m0 = by * 64;
    const __half* Ah = g_ht;
    const __half* Al = g_htl;
    const __half* Bh = g_gw1h;
    const __half* Bl = g_gw1l;

    const int tid   = threadIdx.x;
    const int warp  = tid >> 5;
    const int lane  = tid & 31;
    const int warpM = warp >> 2;
    const int warpN = warp & 3;

    const uint32_t sbase = s2u(smem);

    auto load_stage = [&](int s, int k0) {
        uint32_t aH = sbase + (uint32_t)s * STAGE_BYTES;
        uint32_t aL = aH + TB, bH = aH + 2 * TB, bL = aH + 3 * TB;
        #pragma unroll
        for (int t = 0; t < 2; t++) {
            int id = tid + t * 256;
            int row = id >> 3, c = id & 7;
            uint32_t o = SWZ(row * 128 + c * 16);
            CPA16(aH + o, Ah + (size_t)(m0 + row) * K + k0 + c * 8);
            CPA16(aL + o, Al + (size_t)(m0 + row) * K + k0 + c * 8);
            CPA16(bH + o, Bh + (size_t)(n0 + row) * K + k0 + c * 8);
            CPA16(bL + o, Bl + (size_t)(n0 + row) * K + k0 + c * 8);
        }
    };

    load_stage(0, 0);   CPCOMMIT();
    load_stage(1, BK);  CPCOMMIT();

    float acc[2][2][4] = {};

    for (int i = 0; i < NIT; i++) {
        if (i + 1 < NIT) { CPWAIT1(); } else { CPWAIT0(); }
        __syncthreads();
        if (i + 2 < NIT) { load_stage((i + 2) % STAGES, (i + 2) * BK); CPCOMMIT(); }

        const uint32_t aH = sbase + (uint32_t)(i % STAGES) * STAGE_BYTES;
        const uint32_t aL = aH + TB, bH = aH + 2 * TB, bL = aH + 3 * TB;

        #pragma unroll
        for (int ks = 0; ks < 4; ks++) {
            uint32_t afh[2][4], afl[2][4], bfh[4], bfl[4];
            const int c = ks * 2 + (lane >> 4);
            #pragma unroll
            for (int ii = 0; ii < 2; ii++) {
                int row = warpM * 32 + ii * 16 + (lane & 15);
                uint32_t o = SWZ(row * 128 + c * 16);
                LDSM4(afh[ii], aH + o);
                LDSM4(afl[ii], aL + o);
            }
            {
                int row = warpN * 16 + (lane & 15);
                uint32_t o = SWZ(row * 128 + c * 16);
                LDSM4(bfh, bH + o);
                LDSM4(bfl, bL + o);
            }
            #pragma unroll
            for (int ii = 0; ii < 2; ii++) {
                mma_f16(acc[ii][0], afh[ii], bfh[0], bfh[2]);
                mma_f16(acc[ii][1], afh[ii], bfh[1], bfh[3]);
                mma_f16(acc[ii][0], afh[ii], bfl[0], bfl[2]);
                mma_f16(acc[ii][1], afh[ii], bfl[1], bfl[3]);
                mma_f16(acc[ii][0], afl[ii], bfh[0], bfh[2]);
                mma_f16(acc[ii][1], afl[ii], bfh[1], bfh[3]);
            }
        }
    }

    const int r  = lane >> 2;
    const int c2 = (lane & 3) * 2;
    #pragma unroll
    for (int ii = 0; ii < 2; ii++) {
        int row0 = m0 + warpM * 32 + ii * 16 + r;
        int row1 = row0 + 8;
        #pragma unroll
        for (int j = 0; j < 2; j++) {
            int gcol = n0 + warpN * 16 + j * 8 + c2;
            float b0 = bias[gcol], b1 = bias[gcol + 1];
            float v0 = gelu_erf(acc[ii][j][0] + b0);
            float v1 = gelu_erf(acc[ii][j][1] + b1);
            float v2 = gelu_erf(acc[ii][j][2] + b0);
            float v3 = gelu_erf(acc[ii][j][3] + b1);
            *(float2*)(g_g1 + (size_t)row0 * GH + gcol) = make_float2(v0, v1);
            *(float2*)(g_g1 + (size_t)row1 * GH + gcol) = make_float2(v2, v3);
        }
    }
}

// ===========================================================================
// Expert fp16 GEMM with TMA operand loads: CTA 128x128, warp 64x32, BK=64,
// 3-stage, occ 2.  Compute mainloop identical to the proven R9/R11 kernel.
// A tensormap: dims [K, M, (EOUT ? EE : 1)]; B tensormap: dims [K, N, EE].
// ===========================================================================
template <int K, int N, bool GELU, bool EOUT>
__global__ __launch_bounds__(256, 2)
void hgemm_tma(const __grid_constant__ CUtensorMap tmA,
               const __grid_constant__ CUtensorMap tmB,
               const float* __restrict__ bias,
               void* __restrict__ Cout) {
    constexpr int BK = 64;
    constexpr int NIT = K / BK;
    constexpr int ABYTES = 128 * 128;          // 16 KB per operand tile
    constexpr int STAGE_BYTES = 2 * ABYTES;    // 32 KB
    constexpr int STAGES = 3;

    extern __shared__ __align__(1024) char smem[];
    __shared__ uint64_t mbar[STAGES];

    const int e  = blockIdx.z;
    const int n0 = blockIdx.x * 128;
    const int m0 = blockIdx.y * 128;
    bias += (size_t)e * N;

    const int tid   = threadIdx.x;
    const int warp  = tid >> 5;
    const int lane  = tid & 31;
    const int warpM = warp >> 2;
    const int warpN = warp & 3;
    const int eA    = EOUT ? e : 0;            // GEMM2's A (hid) is per-expert

    const uint32_t sbase = s2u(smem);
    uint32_t mb[STAGES];
    #pragma unroll
    for (int s = 0; s < STAGES; s++) mb[s] = s2u(&mbar[s]);

    if (tid == 0) {
        #pragma unroll
        for (int s = 0; s < STAGES; s++) MBAR_INIT(mb[s], 1);
    }
    __syncthreads();

    if (tid == 0) {
        MBAR_EXPECT(mb[0], STAGE_BYTES);
        TMA_LOAD3(sbase,          &tmA, 0,  m0, eA, mb[0]);
        TMA_LOAD3(sbase + ABYTES, &tmB, 0,  n0, e,  mb[0]);
        MBAR_EXPECT(mb[1], STAGE_BYTES);
        TMA_LOAD3(sbase + STAGE_BYTES,          &tmA, BK, m0, eA, mb[1]);
        TMA_LOAD3(sbase + STAGE_BYTES + ABYTES, &tmB, BK, n0, e,  mb[1]);
    }

    float acc[4][4][4] = {};
    int ph[STAGES] = {0, 0, 0};

    for (int i = 0; i < NIT; i++) {
        const int s = i % STAGES;
        MBAR_WAIT(mb[s], ph[s]);
        ph[s] ^= 1;
        __syncthreads();                        // stage (i+2)%3 free for reuse

        if (i + 2 < NIT && tid == 0) {
            const int b = (i + 2) % STAGES;
            const uint32_t dst = sbase + (uint32_t)b * STAGE_BYTES;
            MBAR_EXPECT(mb[b], STAGE_BYTES);
            TMA_LOAD3(dst,          &tmA, (i + 2) * BK, m0, eA, mb[b]);
            TMA_LOAD3(dst + ABYTES, &tmB, (i + 2) * BK, n0, e,  mb[b]);
        }

        const uint32_t aB = sbase + (uint32_t)s * STAGE_BYTES;
        const uint32_t bB = aB + ABYTES;

        #pragma unroll
        for (int ks = 0; ks < 4; ks++) {
            uint32_t afr[4][4], bfr[2][4];
            const int c = ks * 2 + (lane >> 4);
            #pragma unroll
            for (int ii = 0; ii < 4; ii++) {
                int row = warpM * 64 + ii * 16 + (lane & 15);
                LDSM4(afr[ii], aB + SWZ(row * 128 + c * 16));
            }
            #pragma unroll
            for (int jp = 0; jp < 2; jp++) {
                int row = warpN * 32 + jp * 16 + (lane & 15);
                LDSM4(bfr[jp], bB + SWZ(row * 128 + c * 16));
            }
            #pragma unroll
            for (int ii = 0; ii < 4; ii++) {
                #pragma unroll
                for (int jp = 0; jp < 2; jp++) {
                    mma_f16(acc[ii][jp * 2 + 0], afr[ii], bfr[jp][0], bfr[jp][2]);
                    mma_f16(acc[ii][jp * 2 + 1], afr[ii], bfr[jp][1], bfr[jp][3]);
                }
            }
        }
    }

    const int r  = lane >> 2;
    const int c2 = (lane & 3) * 2;
    #pragma unroll
    for (int ii = 0; ii < 4; ii++) {
        int row0 = m0 + warpM * 64 + ii * 16 + r;
        int row1 = row0 + 8;
        #pragma unroll
        for (int j = 0; j < 4; j++) {
            int gcol = n0 + warpN * 32 + j * 8 + c2;
            float b0 = bias[gcol], b1 = bias[gcol + 1];
            float v0 = acc[ii][j][0] + b0;
            float v1 = acc[ii][j][1] + b1;
            float v2 = acc[ii][j][2] + b0;
            float v3 = acc[ii][j][3] + b1;
            if (GELU) {
                v0 = gelu_erf(v0); v1 = gelu_erf(v1);
                v2 = gelu_erf(v2); v3 = gelu_erf(v3);
            }
            if (EOUT) {
                float* C = (float*)Cout;
                *(float2*)(C + ((size_t)row0 * EE + e) * DD + gcol) = make_float2(v0, v1);
                *(float2*)(C + ((size_t)row1 * EE + e) * DD + gcol) = make_float2(v2, v3);
            } else {
                __half* C = (__half*)Cout;
                *(__half2*)(C + ((size_t)e * BB + row0) * (size_t)N + gcol) =
                    __floats2half2_rn(v0, v1);
                *(__half2*)(C + ((size_t)e * BB + row1) * (size_t)N + gcol) =
                    __floats2half2_rn(v2, v3);
            }
        }
    }
}

// ---------------------------------------------------------------------------
// gating logits + softmax + top-2
// ---------------------------------------------------------------------------
__global__ void gate_kernel(const float* __restrict__ gw2,
                            const float* __restrict__ gb2,
                            float* __restrict__ gate_out) {
    int warp = threadIdx.x >> 5, lane = threadIdx.x & 31;
    int b = blockIdx.x * 8 + warp;
    const float* g1 = g_g1 + (size_t)b * GH;
    float logit[EE];
    #pragma unroll
    for (int e = 0; e < EE; e++) {
        float acc = 0.f;
        for (int k = lane; k < GH; k += 32) acc += g1[k] * gw2[k * EE + e];
        #pragma unroll
        for (int o = 16; o; o >>= 1) acc += __shfl_xor_sync(0xffffffffu, acc, o);
        logit[e] = acc + gb2[e];
    }
    if (lane == 0) {
        float mx = logit[0];
        #pragma unroll
        for (int e = 1; e < EE; e++) mx = fmaxf(mx, logit[e]);
        float p[EE]; float sum = 0.f;
        #pragma unroll
        for (int e = 0; e < EE; e++) { p[e] = expf(logit[e] - mx); sum += p[e]; }
        float invs = 1.0f / sum;
        #pragma unroll
        for (int e = 0; e < EE; e++) {
            p[e] *= invs;
            gate_out[(size_t)b * EE + e] = p[e];
        }
        int i0 = 0;
        #pragma unroll
        for (int e = 1; e < EE; e++) if (p[e] > p[i0]) i0 = e;
        int i1 = (i0 == 0) ? 1 : 0;
        #pragma unroll
        for (int e = 0; e < EE; e++) if (e != i0 && p[e] > p[i1]) i1 = e;
        float w0 = p[i0], w1 = p[i1], s = w0 + w1;
        g_w[b * 2 + 0] = w0 / s;
        g_w[b * 2 + 1] = w1 / s;
        g_i[b * 2 + 0] = i0;
        g_i[b * 2 + 1] = i1;
    }
}

// ---------------------------------------------------------------------------
// combine: weighted sum of top-2 expert outputs (float4 vectorized)
// ---------------------------------------------------------------------------
__global__ __launch_bounds__(192)
void combine_kernel(const float* __restrict__ eo, float* __restrict__ out) {
    int b = blockIdx.x;
    int i0 = g_i[b * 2], i1 = g_i[b * 2 + 1];
    float w0 = g_w[b * 2], w1 = g_w[b * 2 + 1];
    const float4* r0 = (const float4*)(eo + (size_t)b * EE * DD + (size_t)i0 * DD);
    const float4* r1 = (const float4*)(eo + (size_t)b * EE * DD + (size_t)i1 * DD);
    float4* o = (float4*)(out + (size_t)b * DD);
    int t = threadIdx.x;
    float4 a = r0[t], c = r1[t];
    float4 v;
    v.x = w0 * a.x + w1 * c.x;
    v.y = w0 * a.y + w1 * c.y;
    v.z = w0 * a.z + w1 * c.z;
    v.w = w0 * a.w + w1 * c.w;
    o[t] = v;
}

// ---------------------------------------------------------------------------
typedef CUresult (*TmEncodeFn)(CUtensorMap*, CUtensorMapDataType, cuuint32_t,
                               void*, const cuuint64_t*, const cuuint64_t*,
                               const cuuint32_t*, const cuuint32_t*,
                               CUtensorMapInterleave, CUtensorMapSwizzle,
                               CUtensorMapL2promotion, CUtensorMapFloatOOBfill);

static void make_map(TmEncodeFn enc, CUtensorMap* m, void* ptr,
                     uint64_t d0, uint64_t d1, uint64_t d2) {
    cuuint64_t dims[3]    = {d0, d1, d2};
    cuuint64_t strides[2] = {d0 * 2, d0 * d1 * 2};
    cuuint32_t box[3]     = {64, 128, 1};
    cuuint32_t es[3]      = {1, 1, 1};
    enc(m, CU_TENSOR_MAP_DATA_TYPE_FLOAT16, 3, ptr, dims, strides, box, es,
        CU_TENSOR_MAP_INTERLEAVE_NONE, CU_TENSOR_MAP_SWIZZLE_128B,
        CU_TENSOR_MAP_L2_PROMOTION_L2_128B, CU_TENSOR_MAP_FLOAT_OOB_FILL_NONE);
}

extern "C" void kernel_launch(void* const* d_in, const int* in_sizes, int n_in,
                              void* d_out, int out_size) {
    const float* pooler   = (const float*)d_in[0];
    const float* ln_gamma = (const float*)d_in[1];
    const float* ln_beta  = (const float*)d_in[2];
    const float* gw1      = (const float*)d_in[3];
    const float* gb1      = (const float*)d_in[4];
    const float* gw2      = (const float*)d_in[5];
    const float* gb2      = (const float*)d_in[6];
    const float* ew1      = (const float*)d_in[7];
    const float* eb1      = (const float*)d_in[8];
    const float* ew2      = (const float*)d_in[9];
    const float* eb2      = (const float*)d_in[10];

    float* out        = (float*)d_out;
    float* out_result = out;                          // [B, D]
    float* out_gate   = out + (size_t)BB * DD;        // [B, E]
    float* out_eo     = out_gate + (size_t)BB * EE;   // [B, E, D]

    __half *ht_ptr, *hid_ptr, *w1t_ptr, *w2t_ptr;
    cudaGetSymbolAddress((void**)&ht_ptr,  g_ht);
    cudaGetSymbolAddress((void**)&hid_ptr, g_hid);
    cudaGetSymbolAddress((void**)&w1t_ptr, g_w1t);
    cudaGetSymbolAddress((void**)&w2t_ptr, g_w2t);

    // tensor maps (host-side, by-value kernel params; no device alloc)
    TmEncodeFn enc = nullptr;
    cudaDriverEntryPointQueryResult qr;
    cudaGetDriverEntryPoint("cuTensorMapEncodeTiled", (void**)&enc,
                            cudaEnableDefault, &qr);
    CUtensorMap tmA1, tmB1, tmA2, tmB2;
    make_map(enc, &tmA1, ht_ptr,  DD, BB, 1);    // g_ht  [B][D]
    make_map(enc, &tmB1, w1t_ptr, DD, HH, EE);   // g_w1t [e][H][D]
    make_map(enc, &tmA2, hid_ptr, HH, BB, EE);   // g_hid [e][B][H]
    make_map(enc, &tmB2, w2t_ptr, HH, DD, EE);   // g_w2t [e][D][H]

    const int SMEM = 3 * 32768;   // 96 KB
    cudaFuncSetAttribute(hgemm_tma<DD, HH, true,  false>,
                         cudaFuncAttributeMaxDynamicSharedMemorySize, SMEM);
    cudaFuncSetAttribute(hgemm_tma<HH, DD, false, true>,
                         cudaFuncAttributeMaxDynamicSharedMemorySize, SMEM);
    cudaFuncSetAttribute(gate_gemm_kernel,
                         cudaFuncAttributeMaxDynamicSharedMemorySize, SMEM);

    // 1) prep: LN + all weight transposes/splits, fully parallel
    prep_kernel<<<NB_PREP, 256>>>(pooler, ln_gamma, ln_beta, ew1, ew2, gw1);

    // 2) gating hidden (split-fp16, fp32-faithful)
    gate_gemm_kernel<<<(GH / 64) * (BB / 64), 256, SMEM>>>(gb1);

    // 3) gating logits + softmax + top2
    gate_kernel<<<BB / 8, 256>>>(gw2, gb2, out_gate);

    // 4) expert hidden: hid[e] = half(gelu(h @ ew1[e] + eb1[e]))
    hgemm_tma<DD, HH, true, false><<<dim3(HH / 128, BB / 128, EE), 256, SMEM>>>(
        tmA1, tmB1, eb1, hid_ptr);

    // 5) expert outputs: eo[:,e,:] = hid[e] @ ew2[e] + eb2[e]
    hgemm_tma<HH, DD, false, true><<<dim3(DD / 128, BB / 128, EE), 256, SMEM>>>(
        tmA2, tmB2, eb2, out_eo);

    // 6) combine top-2
    combine_kernel<<<BB, 192>>>(out_eo, out_result);
}